// round 6
// baseline (speedup 1.0000x reference)
#include <cuda_runtime.h>

#define BB 8
#define CC 4
#define HH 512
#define WW 512
#define RPW 8                          // rows per warp strip
#define NSTRIPS (HH / RPW)             // 64
#define NPLANE (BB * CC)               // 32
#define NT 128
#define WPB (NT / 32)                  // 4 warps/block
#define NBLK (NPLANE * NSTRIPS * 4 / WPB)   // 2048

typedef unsigned long long ull;

// f32x2 constants: (2.0f,2.0f) and (-1.0f,-1.0f)
#define TWO2  0x4000000040000000ull
#define NEG12 0xBF800000BF800000ull

__device__ float4 g_part[NBLK];
__device__ int g_ctr = 0;

__device__ __forceinline__ float sigm(float x) {
    float t;
    asm("tanh.approx.f32 %0, %1;" : "=f"(t) : "f"(0.5f * x));
    return __fmaf_rn(0.5f, t, 0.5f);
}
__device__ __forceinline__ unsigned prmt(unsigned a, unsigned b, unsigned s) {
    unsigned r;
    asm("prmt.b32 %0, %1, %2, %3;" : "=r"(r) : "r"(a), "r"(b), "r"(s));
    return r;
}
__device__ __forceinline__ ull pk2(float lo, float hi) {
    ull r; asm("mov.b64 %0, {%1, %2};" : "=l"(r) : "f"(lo), "f"(hi)); return r;
}
__device__ __forceinline__ void up2(float& lo, float& hi, ull v) {
    asm("mov.b64 {%0, %1}, %2;" : "=f"(lo), "=f"(hi) : "l"(v));
}
__device__ __forceinline__ ull fma2(ull a, ull b, ull c) {
    ull r; asm("fma.rn.f32x2 %0, %1, %2, %3;" : "=l"(r) : "l"(a), "l"(b), "l"(c)); return r;
}
__device__ __forceinline__ ull add2(ull a, ull b) {
    ull r; asm("add.rn.f32x2 %0, %1, %2;" : "=l"(r) : "l"(a), "l"(b)); return r;
}
__device__ __forceinline__ ull mul2(ull a, ull b) {
    ull r; asm("mul.rn.f32x2 %0, %1, %2;" : "=l"(r) : "l"(a), "l"(b)); return r;
}

struct Row {
    ull s01, s23, d01, d23;      // horizontal sobel partials (probs), packed pairs
    unsigned sb, db;             // packed-byte partials (targets)
};

template <bool DICE>
__device__ __forceinline__ Row fetch(const float* __restrict__ lg,
                                     const float* __restrict__ tg,
                                     int gr, int c0, int lane,
                                     bool lEdge, bool rEdge,
                                     ull& s_pt2, ull& s_p2, int& s_ti)
{
    Row h;
    const bool in = ((unsigned)gr < (unsigned)HH);   // warp-uniform
    if (in) {
        const float* rowp = lg + (size_t)gr * WW + c0;
        const float* rowt = tg + (size_t)gr * WW + c0;
        float4 x  = __ldg((const float4*)rowp);
        float4 tv = __ldg((const float4*)rowt);

        // raw neighbor exchange (independent of MUFU)
        float xl = __shfl_up_sync(0xffffffffu, x.w, 1);
        float xr = __shfl_down_sync(0xffffffffu, x.x, 1);
        if (lane == 0  && lEdge) xl = __ldg(rowp - 1);
        if (lane == 31 && rEdge) xr = __ldg(rowp + 4);

        unsigned q1 = prmt(__float_as_uint(tv.x), __float_as_uint(tv.y), 0x0073u);
        unsigned q2 = prmt(__float_as_uint(tv.z), __float_as_uint(tv.w), 0x7300u);
        unsigned tw = (q1 | q2) & 0x01010101u;
        unsigned twl = __shfl_up_sync(0xffffffffu, tw, 1);
        unsigned twr = __shfl_down_sync(0xffffffffu, tw, 1);
        unsigned tl = twl >> 24, tr = twr & 0xffu;
        if (lane == 0)  tl = lEdge ? (__float_as_uint(__ldg(rowt - 1)) >> 29) : 0u;
        if (lane == 31) tr = rEdge ? (__float_as_uint(__ldg(rowt + 4)) >> 29) : 0u;

        float p0 = sigm(x.x), p1 = sigm(x.y), p2 = sigm(x.z), p3 = sigm(x.w);
        float pl = sigm(xl);
        float pr = sigm(xr);
        if (lane == 0  && !lEdge) pl = 0.f;   // image edge: padded PROBS are 0
        if (lane == 31 && !rEdge) pr = 0.f;

        ull v01 = pk2(p0, p1), v23 = pk2(p2, p3);
        ull l01 = pk2(pl, p0), l23 = pk2(p1, p2);
        ull r01 = pk2(p1, p2), r23 = pk2(p3, pr);
        h.s01 = fma2(TWO2, v01, add2(l01, r01));
        h.s23 = fma2(TWO2, v23, add2(l23, r23));
        h.d01 = fma2(l01, NEG12, r01);        // right - left
        h.d23 = fma2(l23, NEG12, r23);

        unsigned wl = (tw << 8) | tl;
        unsigned wr = (tw >> 8) | (tr << 24);
        h.sb = wl + 2u * tw + wr;             // lanes in [0,4]
        h.db = (wr + 0x02020202u) - wl;       // lanes in [1,3] (bias +2)

        if (DICE) {
            s_pt2 = fma2(v01, pk2(tv.x, tv.y), s_pt2);
            s_pt2 = fma2(v23, pk2(tv.z, tv.w), s_pt2);
            s_p2  = add2(s_p2, v01);
            s_p2  = add2(s_p2, v23);
            s_ti += __popc(tw);               // bytes are 0/1
        }
    } else {
        h.s01 = h.s23 = h.d01 = h.d23 = 0ull; // (0.0f,0.0f) bit pattern
        h.sb = 0u;
        h.db = 0x02020202u;                   // biased zero
    }
    return h;
}

__device__ __forceinline__ int combine(const Row& h0, const Row& h1, const Row& h2)
{
    ull gx01 = fma2(TWO2, h1.d01, add2(h0.d01, h2.d01));
    ull gx23 = fma2(TWO2, h1.d23, add2(h0.d23, h2.d23));
    ull gy01 = fma2(h0.s01, NEG12, h2.s01);
    ull gy23 = fma2(h0.s23, NEG12, h2.s23);
    ull m01 = fma2(gx01, gx01, mul2(gy01, gy01));
    ull m23 = fma2(gx23, gx23, mul2(gy23, gy23));
    float f0, f1, f2, f3;
    up2(f0, f1, m01);
    up2(f2, f3, m23);
    bool pb0 = f0 > 0.25f, pb1 = f1 > 0.25f, pb2 = f2 > 0.25f, pb3 = f3 > 0.25f;

    unsigned hx = h0.db + 2u * h1.db + h2.db;     // ==8 per lane <=> hx_true==0
    unsigned hy = (h2.sb + 0x04040404u) - h0.sb;  // ==4 per lane <=> hy_true==0
    unsigned cmb = (hx ^ 0x08080808u) | (hy ^ 0x04040404u);

    int m = 0;
    m += (int)(pb0 != ((cmb & 0x000000FFu) != 0));
    m += (int)(pb1 != ((cmb & 0x0000FF00u) != 0));
    m += (int)(pb2 != ((cmb & 0x00FF0000u) != 0));
    m += (int)(pb3 != ((cmb >> 24) != 0));
    return m;
}

__global__ __launch_bounds__(NT, 9) void loss_fused(
    const float* __restrict__ logits, const float* __restrict__ targets,
    const float* __restrict__ cw, float* __restrict__ out)
{
    __shared__ float red[WPB][4];
    __shared__ float s_dice[NPLANE];
    __shared__ float s_mm[NPLANE];
    __shared__ int s_isLast;

    const int lane = threadIdx.x & 31;
    const int gw = blockIdx.x * WPB + (threadIdx.x >> 5);
    const int cg    = gw & 3;                    // column group 0..3
    const int strip = (gw >> 2) & (NSTRIPS - 1); // 0..63
    const int plane = gw >> 8;                   // 0..31
    const int c0 = cg * 128 + lane * 4;
    const bool lEdge = (cg > 0);
    const bool rEdge = (cg < 3);
    const int row0 = strip * RPW;

    const float* lg = logits  + (size_t)plane * HH * WW;
    const float* tg = targets + (size_t)plane * HH * WW;

    ull s_pt2 = 0ull, s_p2 = 0ull;
    int s_ti = 0, s_mi = 0;

    Row h0 = fetch<false>(lg, tg, row0 - 1, c0, lane, lEdge, rEdge, s_pt2, s_p2, s_ti);
    Row h1 = fetch<true >(lg, tg, row0,     c0, lane, lEdge, rEdge, s_pt2, s_p2, s_ti);
    #pragma unroll
    for (int k = 0; k < RPW - 1; k++) {
        Row h2 = fetch<true>(lg, tg, row0 + k + 1, c0, lane, lEdge, rEdge, s_pt2, s_p2, s_ti);
        s_mi += combine(h0, h1, h2);
        h0 = h1; h1 = h2;
    }
    {
        Row h2 = fetch<false>(lg, tg, row0 + RPW, c0, lane, lEdge, rEdge, s_pt2, s_p2, s_ti);
        s_mi += combine(h0, h1, h2);
    }

    // unpack accumulators
    float pa, pb, pta, ptb;
    up2(pa, pb, s_p2);
    up2(pta, ptb, s_pt2);
    float s_p = pa + pb;
    float s_pt = pta + ptb;
    float s_t = (float)s_ti, s_m = (float)s_mi;

    #pragma unroll
    for (int o = 16; o > 0; o >>= 1) {
        s_pt += __shfl_down_sync(0xffffffffu, s_pt, o);
        s_p  += __shfl_down_sync(0xffffffffu, s_p,  o);
        s_t  += __shfl_down_sync(0xffffffffu, s_t,  o);
        s_m  += __shfl_down_sync(0xffffffffu, s_m,  o);
    }
    int w = threadIdx.x >> 5;
    if (lane == 0) {
        red[w][0] = s_pt; red[w][1] = s_p; red[w][2] = s_t; red[w][3] = s_m;
    }
    __syncthreads();
    if (threadIdx.x == 0) {
        float a = 0.f, b = 0.f, c2 = 0.f, d = 0.f;
        #pragma unroll
        for (int j = 0; j < WPB; j++) {
            a += red[j][0]; b += red[j][1]; c2 += red[j][2]; d += red[j][3];
        }
        g_part[blockIdx.x] = make_float4(a, b, c2, d);
        __threadfence();
        int v = atomicAdd(&g_ctr, 1);
        s_isLast = (v == NBLK - 1);
    }
    __syncthreads();

    if (s_isLast) {
        __threadfence();
        int tid = threadIdx.x;
        if (tid < NPLANE) {
            float a = 0.f, b = 0.f, c2 = 0.f, m = 0.f;
            #pragma unroll 8
            for (int s = 0; s < NBLK / NPLANE; s++) {
                float4 v = g_part[tid * (NBLK / NPLANE) + s];
                a += v.x; b += v.y; c2 += v.z; m += v.w;
            }
            s_dice[tid] = (2.0f * a + 1.0f) / (b + c2 + 1.0f);  // SMOOTH=1
            s_mm[tid] = m;
        }
        __syncthreads();
        if (tid == 0) {
            float mt = 0.0f;
            #pragma unroll
            for (int j = 0; j < NPLANE; j++) mt += s_mm[j];

            float wsum = 0.0f, dl = 0.0f;
            #pragma unroll
            for (int c = 0; c < CC; c++) {
                float acc = 0.0f;
                #pragma unroll
                for (int b = 0; b < BB; b++) acc += s_dice[b * CC + c];
                dl += cw[c] * (1.0f - acc / (float)BB);
                wsum += cw[c];
            }
            dl /= wsum;
            float bl = 100.0f * mt / (float)((long long)BB * CC * HH * WW);
            out[0] = 0.7f * dl + 0.3f * bl;
            g_ctr = 0;   // reset for next graph replay
        }
    }
}

extern "C" void kernel_launch(void* const* d_in, const int* in_sizes, int n_in,
                              void* d_out, int out_size)
{
    const float* logits  = (const float*)d_in[0];
    const float* targets = (const float*)d_in[1];
    const float* cw      = (const float*)d_in[2];

    loss_fused<<<NBLK, NT>>>(logits, targets, cw, (float*)d_out);
}